// round 10
// baseline (speedup 1.0000x reference)
#include <cuda_runtime.h>
#include <cuda_fp16.h>
#include <mma.h>

using namespace nvcuda;

#define Bsz  4096
#define Nseq 512
#define Csz  512
#define PHId 128
#define H1d  512
#define H2d  256

// Scratch (__device__ globals; no allocations allowed)
__device__ __half g_hist [Bsz * Csz];    // 4 MB
__device__ __half g_h1   [Bsz * H1d];    // 4 MB
__device__ float  g_part [4 * Bsz];
__device__ __half g_Wc   [Csz * H1d];    // Wc = Wphi @ W1 (fp16)
__device__ __half g_W2   [H1d * H2d];
__device__ float  g_b1eff[H1d];
__device__ int    g_flags[256];          // sync counters (memset each call)

// flag layout
#define FD_HIST 0     // [64] target 16
#define FD_WC   64    // [8]  target 8
#define FD_B1   72    //      target 1
#define FD_W2   73    //      target 32
#define FD_H1   74    // [64] target 8
#define FD_PART 138   // [64] target 4

// block ranges (bid order == dependency order; consumers wait only on lower bids)
#define NHIST 1024
#define WC0   1024
#define W20   1088
#define B10   1120
#define G10   1121
#define G20   1633
#define RD0   1889
#define NBLK  1921

// ---------------------------------------------------------------------------
__device__ __forceinline__ void cp_async16(void* smem, const void* gmem) {
    unsigned s = (unsigned)__cvta_generic_to_shared(smem);
    asm volatile("cp.async.cg.shared.global [%0], [%1], 16;\n" :: "r"(s), "l"(gmem));
}
__device__ __forceinline__ void cp_commit() {
    asm volatile("cp.async.commit_group;\n");
}
template <int NN>
__device__ __forceinline__ void cp_wait() {
    asm volatile("cp.async.wait_group %0;\n" :: "n"(NN));
}

// release: all threads fenced their stores, barrier, tid0 bumps counter
__device__ __forceinline__ void release(int* flag) {
    __threadfence();
    __syncthreads();
    if (threadIdx.x == 0) atomicAdd(flag, 1);
}
// acquire: tid0 spins, barrier, all threads fence (flushes stale L1)
__device__ __forceinline__ void spin1(volatile int* p, int tgt) {
    while (*p < tgt) __nanosleep(64);
}

// ---------------------------------------------------------------------------
// Shared GEMM body: BM=BN=BK=64, 128 threads, 4 warps (2x2), warp tile 32x32,
// 2-stage cp.async pipeline, one barrier per k-iter. fp16 in, fp32 acc.
// ---------------------------------------------------------------------------
template <bool FUSED>
__device__ __forceinline__ void gemm_body(char* smraw,
                                          const __half* __restrict__ A,
                                          const __half* __restrict__ B,
                                          const float* __restrict__ bias,
                                          const float* __restrict__ w3,
                                          __half* __restrict__ C,
                                          float* __restrict__ partRow,
                                          int rowBase, int colBase, int N, int K)
{
    __half* sh = reinterpret_cast<__half*>(smraw);
    const int tid = threadIdx.x, warp = tid >> 5;
    const int wr = warp & 1, wc = warp >> 1;
    const int lr = tid >> 3, lc = (tid & 7) << 3;

    auto SA = [&](int s, int r) { return sh + (s * 64 + r) * 72; };
    auto SB = [&](int s, int r) { return sh + 9216 + (s * 64 + r) * 72; };

    auto load_tile = [&](int s, int kt) {
        const __half* Ak = A + (size_t)rowBase * K + kt * 64;
#pragma unroll
        for (int r = 0; r < 4; r++)
            cp_async16(SA(s, lr + 16 * r) + lc, Ak + (size_t)(lr + 16 * r) * K + lc);
        const __half* Bk = B + (size_t)(kt * 64) * N + colBase;
#pragma unroll
        for (int r = 0; r < 4; r++)
            cp_async16(SB(s, lr + 16 * r) + lc, Bk + (size_t)(lr + 16 * r) * N + lc);
    };

    wmma::fragment<wmma::accumulator, 16, 16, 16, float> acc[2][2];
#pragma unroll
    for (int i = 0; i < 2; i++)
#pragma unroll
        for (int j = 0; j < 2; j++) wmma::fill_fragment(acc[i][j], 0.f);

    const int KT = K / 64;
    load_tile(0, 0); cp_commit();

    for (int kt = 0; kt < KT; kt++) {
        cp_wait<0>();
        __syncthreads();
        if (kt + 1 < KT) load_tile((kt + 1) & 1, kt + 1);
        cp_commit();

        const int s = kt & 1;
#pragma unroll
        for (int kk = 0; kk < 4; kk++) {
            wmma::fragment<wmma::matrix_a, 16, 16, 16, __half, wmma::row_major> af[2];
            wmma::fragment<wmma::matrix_b, 16, 16, 16, __half, wmma::row_major> bf[2];
#pragma unroll
            for (int i = 0; i < 2; i++)
                wmma::load_matrix_sync(af[i], SA(s, wr * 32 + i * 16) + kk * 16, 72);
#pragma unroll
            for (int j = 0; j < 2; j++)
                wmma::load_matrix_sync(bf[j], SB(s, kk * 16) + wc * 32 + j * 16, 72);
#pragma unroll
            for (int i = 0; i < 2; i++)
#pragma unroll
                for (int j = 0; j < 2; j++)
                    wmma::mma_sync(acc[i][j], af[i], bf[j], acc[i][j]);
        }
    }
    __syncthreads();

    float* Cs = reinterpret_cast<float*>(smraw);       // [64][68]
#pragma unroll
    for (int i = 0; i < 2; i++)
#pragma unroll
        for (int j = 0; j < 2; j++)
            wmma::store_matrix_sync(&Cs[(wr * 32 + i * 16) * 68 + wc * 32 + j * 16],
                                    acc[i][j], 68, wmma::mem_row_major);
    __syncthreads();

    if (!FUSED) {
#pragma unroll
        for (int e = tid; e < 64 * 8; e += 128) {
            const int r = e >> 3, c = (e & 7) << 3;
            __half h8[8];
#pragma unroll
            for (int q = 0; q < 8; q++)
                h8[q] = __float2half(fmaxf(Cs[r * 68 + c + q] + bias[colBase + c + q], 0.f));
            *reinterpret_cast<int4*>(&C[(size_t)(rowBase + r) * N + colBase + c]) =
                *reinterpret_cast<int4*>(h8);
        }
    } else {
        float* sp = reinterpret_cast<float*>(smraw + 17408);   // [64][2]
        const int r = tid >> 1, sc = (tid & 1) << 5;
        float v = 0.f;
#pragma unroll
        for (int i = 0; i < 32; i++) {
            const float h = fmaxf(Cs[r * 68 + sc + i] + bias[colBase + sc + i], 0.f);
            v = fmaf(h, w3[colBase + sc + i], v);
        }
        sp[r * 2 + (tid & 1)] = v;
        __syncthreads();
        if (tid < 64) partRow[tid] = sp[tid * 2] + sp[tid * 2 + 1];
    }
}

// ---------------------------------------------------------------------------
// Mega kernel: all phases, device-side dependencies (flag counters).
// ---------------------------------------------------------------------------
__global__ void __launch_bounds__(128, 6)
mega_kernel(const int* __restrict__ x,
            const float* __restrict__ Wphi, const float* __restrict__ bphi,
            const float* __restrict__ W1,   const float* __restrict__ b1,
            const float* __restrict__ W2,   const float* __restrict__ b2,
            const float* __restrict__ W3,   const float* __restrict__ b3,
            float* __restrict__ out)
{
    __shared__ __align__(16) char smraw[36864];
    const int tid = threadIdx.x;
    const int bid = blockIdx.x;
    volatile int* vf = g_flags;

    if (bid < NHIST) {
        // ---- histogram: 4 rows/block, one warp per row ----
        int* hs = reinterpret_cast<int*>(smraw);       // [4][512]
#pragma unroll
        for (int i = 0; i < 4; i++)
            *reinterpret_cast<int4*>(&hs[(i * 128 + tid) * 4]) = make_int4(0, 0, 0, 0);
        __syncthreads();

        const int warp = tid >> 5, lane = tid & 31;
        const int row = bid * 4 + warp;
        const int4* xr = reinterpret_cast<const int4*>(x + (size_t)row * Nseq);
        int* hw = hs + warp * Csz;
#pragma unroll
        for (int i = 0; i < 4; i++) {
            const int4 v = xr[lane + i * 32];
            atomicAdd(&hw[v.x], 1); atomicAdd(&hw[v.y], 1);
            atomicAdd(&hw[v.z], 1); atomicAdd(&hw[v.w], 1);
        }
        __syncthreads();

        __half* dst = g_hist + (size_t)bid * 4 * Csz;
#pragma unroll
        for (int q = 0; q < 2; q++) {
            const int e0 = tid * 16 + q * 8;
            __half h8[8];
#pragma unroll
            for (int j = 0; j < 8; j++) h8[j] = __float2half((float)hs[e0 + j]);
            *reinterpret_cast<int4*>(&dst[e0]) = *reinterpret_cast<int4*>(h8);
        }
        release(&g_flags[FD_HIST + (bid >> 4)]);
    } else if (bid < W20) {
        // ---- Wc = Wphi @ W1 (HMMA), 64x64 tile ----
        const int cb = bid - WC0;
        const int tr = (cb >> 3) * 64, tcc = (cb & 7) * 64;
        __half* sA = reinterpret_cast<__half*>(smraw);          // ld 136
        __half* sB = reinterpret_cast<__half*>(smraw + 17408);  // ld 72
        float*  sC = reinterpret_cast<float*>(smraw);           // ld 68 (aliases sA)

#pragma unroll
        for (int i = 0; i < 16; i++) {
            const int idx = i * 128 + tid;
            const int r = idx >> 5, c4 = (idx & 31) << 2;
            const float4 v = *reinterpret_cast<const float4*>(&Wphi[(size_t)(tr + r) * PHId + c4]);
            __half h4[4] = {__float2half(v.x), __float2half(v.y),
                            __float2half(v.z), __float2half(v.w)};
            *reinterpret_cast<uint2*>(&sA[r * 136 + c4]) = *reinterpret_cast<uint2*>(h4);
        }
#pragma unroll
        for (int i = 0; i < 16; i++) {
            const int idx = i * 128 + tid;
            const int r = idx >> 4, c4 = (idx & 15) << 2;
            const float4 v = *reinterpret_cast<const float4*>(&W1[(size_t)r * H1d + tcc + c4]);
            __half h4[4] = {__float2half(v.x), __float2half(v.y),
                            __float2half(v.z), __float2half(v.w)};
            *reinterpret_cast<uint2*>(&sB[r * 72 + c4]) = *reinterpret_cast<uint2*>(h4);
        }
        __syncthreads();

        const int wcg = tid >> 5;        // 4 warps -> 16-col groups
        wmma::fragment<wmma::accumulator, 16, 16, 16, float> ac[4];
#pragma unroll
        for (int i = 0; i < 4; i++) wmma::fill_fragment(ac[i], 0.f);
#pragma unroll
        for (int k = 0; k < 8; k++) {
            wmma::fragment<wmma::matrix_b, 16, 16, 16, __half, wmma::row_major> bf;
            wmma::load_matrix_sync(bf, &sB[(k * 16) * 72 + wcg * 16], 72);
#pragma unroll
            for (int i = 0; i < 4; i++) {
                wmma::fragment<wmma::matrix_a, 16, 16, 16, __half, wmma::row_major> af;
                wmma::load_matrix_sync(af, &sA[(i * 16) * 136 + k * 16], 136);
                wmma::mma_sync(ac[i], af, bf, ac[i]);
            }
        }
        __syncthreads();
#pragma unroll
        for (int i = 0; i < 4; i++)
            wmma::store_matrix_sync(&sC[(i * 16) * 68 + wcg * 16], ac[i], 68,
                                    wmma::mem_row_major);
        __syncthreads();
#pragma unroll
        for (int e = tid; e < 64 * 8; e += 128) {
            const int r = e >> 3, c = (e & 7) << 3;
            __half h8[8];
#pragma unroll
            for (int q = 0; q < 8; q++) h8[q] = __float2half(sC[r * 68 + c + q]);
            *reinterpret_cast<int4*>(&g_Wc[(size_t)(tr + r) * H1d + tcc + c]) =
                *reinterpret_cast<int4*>(h8);
        }
        release(&g_flags[FD_WC + (cb & 7)]);
    } else if (bid < B10) {
        // ---- W2 fp32 -> fp16 ----
        const int cb = bid - W20;
#pragma unroll
        for (int i = 0; i < 8; i++) {
            const int idx = ((cb * 128 + tid) * 8 + i * 0) + (cb * 1024 + tid + i * 128) * 0; // (unused)
            (void)idx;
        }
        const int t0 = cb * 128 + tid;   // 4096 threads total, 131072 elems
#pragma unroll
        for (int i = 0; i < 8; i++) {
            const int e4 = t0 + i * 4096;          // float4 index, 32768 total
            const float4 v = *reinterpret_cast<const float4*>(&W2[e4 * 4]);
            __half h4[4] = {__float2half(v.x), __float2half(v.y),
                            __float2half(v.z), __float2half(v.w)};
            *reinterpret_cast<uint2*>(&g_W2[e4 * 4]) = *reinterpret_cast<uint2*>(h4);
        }
        release(&g_flags[FD_W2]);
    } else if (bid < G10) {
        // ---- b1_eff ----
#pragma unroll
        for (int q = 0; q < 4; q++) {
            const int o = tid * 4 + q;
            float s = 0.f;
            for (int k = 0; k < PHId; k++) s = fmaf(bphi[k], W1[k * H1d + o], s);
            g_b1eff[o] = b1[o] + (float)Nseq * s;
        }
        release(&g_flags[FD_B1]);
    } else if (bid < G20) {
        // ---- gemm1: h1 = relu(hist @ Wc + b1eff) ----
        const int t = bid - G10;
        const int rowb = t >> 3, colb = t & 7;
        if (tid == 0) {
            spin1(&vf[FD_HIST + rowb], 16);
            spin1(&vf[FD_WC + colb], 8);
            spin1(&vf[FD_B1], 1);
        }
        __syncthreads();
        __threadfence();
        gemm_body<false>(smraw, g_hist, g_Wc, g_b1eff, nullptr,
                         g_h1, nullptr, rowb * 64, colb * 64, H1d, Csz);
        release(&g_flags[FD_H1 + rowb]);
    } else if (bid < RD0) {
        // ---- gemm2 fused: partials of relu(h1@W2+b2) . W3 ----
        const int t = bid - G20;
        const int rowb = t >> 2, colb = t & 3;
        if (tid == 0) {
            spin1(&vf[FD_H1 + rowb], 8);
            spin1(&vf[FD_W2], 32);
        }
        __syncthreads();
        __threadfence();
        gemm_body<true>(smraw, g_h1, g_W2, b2, W3,
                        nullptr, g_part + (size_t)colb * Bsz + rowb * 64,
                        rowb * 64, colb * 64, H2d, H1d);
        release(&g_flags[FD_PART + rowb]);
    } else {
        // ---- final reduce: 32 blocks x 128 rows ----
        const int base = (bid - RD0) * 128;
        const int rb0 = base >> 6;
        if (tid == 0) {
            spin1(&vf[FD_PART + rb0], 4);
            spin1(&vf[FD_PART + rb0 + 1], 4);
        }
        __syncthreads();
        __threadfence();
        const int row = base + tid;
        const float s = (__ldcg(&g_part[row]) + __ldcg(&g_part[Bsz + row]))
                      + (__ldcg(&g_part[2 * Bsz + row]) + __ldcg(&g_part[3 * Bsz + row]));
        out[row] = s + b3[0];
    }
}

// ---------------------------------------------------------------------------
extern "C" void kernel_launch(void* const* d_in, const int* in_sizes, int n_in,
                              void* d_out, int out_size)
{
    const int*   x    = (const int*)  d_in[0];
    const float* Wphi = (const float*)d_in[1];
    const float* bphi = (const float*)d_in[2];
    const float* W1   = (const float*)d_in[3];
    const float* b1   = (const float*)d_in[4];
    const float* W2   = (const float*)d_in[5];
    const float* b2   = (const float*)d_in[6];
    const float* W3   = (const float*)d_in[7];
    const float* b3   = (const float*)d_in[8];
    float* out = (float*)d_out;

    void* flags_p;
    cudaGetSymbolAddress(&flags_p, g_flags);
    cudaMemsetAsync(flags_p, 0, 256 * sizeof(int), 0);

    mega_kernel<<<NBLK, 128>>>(x, Wphi, bphi, W1, b1, W2, b2, W3, b3, out);
}

// round 11
// speedup vs baseline: 1.3260x; 1.3260x over previous
#include <cuda_runtime.h>
#include <cuda_fp16.h>
#include <mma.h>

using namespace nvcuda;

#define Bsz  4096
#define Nseq 512
#define Csz  512
#define PHId 128
#define H1d  512
#define H2d  256

// Scratch (__device__ globals; no allocations allowed)
__device__ __half g_hist [Bsz * Csz];    // 4 MB   per-row label histogram (fp16, exact)
__device__ __half g_h1   [Bsz * H1d];    // 4 MB
__device__ float  g_part [4 * Bsz];      // partial dots (deterministic reduce)
__device__ __half g_Wc   [Csz * H1d];    // 512 KB  Wc = Wphi @ W1 (fp16)
__device__ __half g_W2   [H1d * H2d];
__device__ float  g_b1eff[H1d];          // b1 + 512 * (b_phi @ W1), exact fp32

// ---------------------------------------------------------------------------
// cp.async helpers (LDGSTS, 16B)
// ---------------------------------------------------------------------------
__device__ __forceinline__ void cp_async16(void* smem, const void* gmem) {
    unsigned s = (unsigned)__cvta_generic_to_shared(smem);
    asm volatile("cp.async.cg.shared.global [%0], [%1], 16;\n" :: "r"(s), "l"(gmem));
}
__device__ __forceinline__ void cp_commit() {
    asm volatile("cp.async.commit_group;\n");
}
template <int NN>
__device__ __forceinline__ void cp_wait() {
    asm volatile("cp.async.wait_group %0;\n" :: "n"(NN));
}

// ---------------------------------------------------------------------------
// Prep kernel, block ranges:
//   [0,512)   : per-row histograms (8 rows/block, smem atomics) -> g_hist fp16
//   [512,576) : Wc = Wphi @ W1 via wmma HMMA (fp16 in, fp32 acc), 64x64/block
//   [576,608) : W2 fp32 -> fp16 convert
//   608       : b1_eff = b1 + 512*(b_phi @ W1) in fp32
// ---------------------------------------------------------------------------
__global__ void __launch_bounds__(256) prep_kernel(const int* __restrict__ x,
                                                   const float* __restrict__ Wphi,
                                                   const float* __restrict__ W1,
                                                   const float* __restrict__ W2,
                                                   const float* __restrict__ bphi,
                                                   const float* __restrict__ b1)
{
    cudaTriggerProgrammaticLaunchCompletion();   // let gemm1 pre-launch
    __shared__ __align__(16) char praw[35840];   // 35 KB, aliased per branch
    const int tid = threadIdx.x;

    if (blockIdx.x < 512) {
        int* hs = reinterpret_cast<int*>(praw);  // [8][512]
#pragma unroll
        for (int i = 0; i < 4; i++)
            reinterpret_cast<int4*>(hs)[tid + i * 256] = make_int4(0, 0, 0, 0);
        __syncthreads();

        const int warp = tid >> 5, lane = tid & 31;
        const int row = blockIdx.x * 8 + warp;
        const int4* xr = reinterpret_cast<const int4*>(x + (size_t)row * Nseq);
        int* hw = hs + warp * Csz;
#pragma unroll
        for (int i = 0; i < 4; i++) {            // 128 int4 per row
            const int4 v = xr[lane + i * 32];
            atomicAdd(&hw[v.x], 1);
            atomicAdd(&hw[v.y], 1);
            atomicAdd(&hw[v.z], 1);
            atomicAdd(&hw[v.w], 1);
        }
        __syncthreads();

        // vectorized fp16 conversion: 1024 int4 -> 1024 x 8B stores
        __half* dst = g_hist + (size_t)blockIdx.x * 8 * Csz;
#pragma unroll
        for (int i = 0; i < 4; i++) {
            const int e4 = tid + i * 256;
            const int4 c = reinterpret_cast<const int4*>(hs)[e4];
            __half h4[4] = {__float2half((float)c.x), __float2half((float)c.y),
                            __float2half((float)c.z), __float2half((float)c.w)};
            *reinterpret_cast<uint2*>(&dst[e4 * 4]) = *reinterpret_cast<uint2*>(h4);
        }
    } else if (blockIdx.x < 576) {
        // Wc tile 64x64, K=128, tensor cores. smem: A[64][136]h, B[128][72]h
        const int cb = blockIdx.x - 512;               // 0..63 -> 8x8 tiles
        const int tr = (cb >> 3) * 64, tcc = (cb & 7) * 64;
        __half* sA = reinterpret_cast<__half*>(praw);           // ld 136
        __half* sB = reinterpret_cast<__half*>(praw + 17408);   // ld 72
        float*  sC = reinterpret_cast<float*>(praw);            // ld 68 (aliases sA)

#pragma unroll
        for (int i = 0; i < 8; i++) {
            const int idx = i * 256 + tid;
            const int r = idx >> 5, c4 = (idx & 31) << 2;
            const float4 v = *reinterpret_cast<const float4*>(
                &Wphi[(size_t)(tr + r) * PHId + c4]);
            __half h4[4] = {__float2half(v.x), __float2half(v.y),
                            __float2half(v.z), __float2half(v.w)};
            *reinterpret_cast<uint2*>(&sA[r * 136 + c4]) = *reinterpret_cast<uint2*>(h4);
        }
#pragma unroll
        for (int i = 0; i < 8; i++) {
            const int idx = i * 256 + tid;
            const int r = idx >> 4, c4 = (idx & 15) << 2;
            const float4 v = *reinterpret_cast<const float4*>(
                &W1[(size_t)r * H1d + tcc + c4]);
            __half h4[4] = {__float2half(v.x), __float2half(v.y),
                            __float2half(v.z), __float2half(v.w)};
            *reinterpret_cast<uint2*>(&sB[r * 72 + c4]) = *reinterpret_cast<uint2*>(h4);
        }
        __syncthreads();

        // 8 warps: 2 row-groups x 4 col-groups; warp tile 32x16
        const int wrp = tid >> 5, wr2 = wrp & 1, wc2 = wrp >> 1;
        wmma::fragment<wmma::accumulator, 16, 16, 16, float> ac[2];
        wmma::fill_fragment(ac[0], 0.f);
        wmma::fill_fragment(ac[1], 0.f);
#pragma unroll
        for (int k = 0; k < 8; k++) {
            wmma::fragment<wmma::matrix_a, 16, 16, 16, __half, wmma::row_major> af[2];
            wmma::fragment<wmma::matrix_b, 16, 16, 16, __half, wmma::row_major> bf;
            wmma::load_matrix_sync(af[0], &sA[(wr2 * 32) * 136 + k * 16], 136);
            wmma::load_matrix_sync(af[1], &sA[(wr2 * 32 + 16) * 136 + k * 16], 136);
            wmma::load_matrix_sync(bf, &sB[(k * 16) * 72 + wc2 * 16], 72);
            wmma::mma_sync(ac[0], af[0], bf, ac[0]);
            wmma::mma_sync(ac[1], af[1], bf, ac[1]);
        }
        __syncthreads();       // done reading sA before aliasing as sC
        wmma::store_matrix_sync(&sC[(wr2 * 32) * 68 + wc2 * 16], ac[0], 68,
                                wmma::mem_row_major);
        wmma::store_matrix_sync(&sC[(wr2 * 32 + 16) * 68 + wc2 * 16], ac[1], 68,
                                wmma::mem_row_major);
        __syncthreads();

#pragma unroll
        for (int e = tid; e < 64 * 8; e += 256) {
            const int r = e >> 3, c = (e & 7) << 3;
            __half h8[8];
#pragma unroll
            for (int q = 0; q < 8; q++) h8[q] = __float2half(sC[r * 68 + c + q]);
            *reinterpret_cast<int4*>(&g_Wc[(size_t)(tr + r) * H1d + tcc + c]) =
                *reinterpret_cast<int4*>(h8);
        }
    } else if (blockIdx.x < 608) {
        // W2 convert: 8192 threads, 32768 float4 -> 4 per thread
        const int t = (blockIdx.x - 576) * 256 + tid;
#pragma unroll
        for (int i = 0; i < 4; i++) {
            const int e4 = t + i * 8192;
            const float4 v = reinterpret_cast<const float4*>(W2)[e4];
            __half h4[4] = {__float2half(v.x), __float2half(v.y),
                            __float2half(v.z), __float2half(v.w)};
            *reinterpret_cast<uint2*>(&g_W2[e4 * 4]) = *reinterpret_cast<uint2*>(h4);
        }
    } else {
#pragma unroll
        for (int o = tid; o < H1d; o += 256) {
            float s = 0.f;
            for (int k = 0; k < PHId; k++) s = fmaf(bphi[k], W1[k * H1d + o], s);
            g_b1eff[o] = b1[o] + (float)Nseq * s;
        }
    }
}

// ---------------------------------------------------------------------------
// Pipelined fp16 tensor-core GEMM, fp32 accumulate, fused bias+ReLU epilogue.
// BM=64, BN=64, BK=64; 128 threads = 4 warps (2x2), warp tile 32x32.
// 2-stage cp.async pipeline, ONE __syncthreads per k-iteration.
// PDL: gemm1 (FUSED=0) gridsyncs on prep, THEN triggers (so gemm2 may safely
// read prep outputs in its prelude). gemm2 (FUSED=1) triggers at top (reduce
// prelude touches only harness inputs), preloads w3/bias, then gridsyncs.
// ---------------------------------------------------------------------------
template <bool FUSED>
__global__ void __launch_bounds__(128) gemm_tc(const __half* __restrict__ A,
                                               const __half* __restrict__ B,
                                               const float* __restrict__ bias,
                                               const float* __restrict__ W3,
                                               __half* __restrict__ C,
                                               int M, int N, int K)
{
    constexpr int BM = 64, BN = 64, BK = 64, T = 128;
    __shared__ __align__(16) union USM {
        struct { __half A[2][BM][BK + 8]; __half B[2][BK][BN + 8]; } in;   // 36 KB
        float Cs[BM][BN + 4];
    } sm;
    __shared__ float w3s[BN];
    __shared__ float bs[BN];
    __shared__ float sp[BM][2];

    const int tid  = threadIdx.x;
    const int warp = tid >> 5;
    const int wr   = warp & 1;      // row group: 32 rows
    const int wc   = warp >> 1;     // col group: 32 cols
    const int rowBase = blockIdx.y * BM;
    const int colBase = blockIdx.x * BN;

    if (FUSED) {
        cudaTriggerProgrammaticLaunchCompletion();     // reduce may pre-launch
        if (tid < BN) {                                 // harness inputs: safe pre-sync
            w3s[tid] = W3[colBase + tid];
            bs[tid]  = bias[colBase + tid];
        }
        cudaGridDependencySynchronize();                // wait for gemm1 (h1)
    } else {
        cudaGridDependencySynchronize();                // wait for prep
        cudaTriggerProgrammaticLaunchCompletion();      // now gemm2 may pre-launch
    }

    // loader map: 64 rows x 8 chunks(16B) = 512 chunks, 4 per thread
    const int lr = tid >> 3, lc = (tid & 7) << 3;

    auto load_tile = [&](int s, int kt) {
        const __half* Ak = A + (size_t)rowBase * K + kt * BK;
#pragma unroll
        for (int r = 0; r < 4; r++)
            cp_async16(&sm.in.A[s][lr + 16 * r][lc], Ak + (size_t)(lr + 16 * r) * K + lc);
        const __half* Bk = B + (size_t)(kt * BK) * N + colBase;
#pragma unroll
        for (int r = 0; r < 4; r++)
            cp_async16(&sm.in.B[s][lr + 16 * r][lc], Bk + (size_t)(lr + 16 * r) * N + lc);
    };

    wmma::fragment<wmma::accumulator, 16, 16, 16, float> acc[2][2];
#pragma unroll
    for (int i = 0; i < 2; i++)
#pragma unroll
        for (int j = 0; j < 2; j++) wmma::fill_fragment(acc[i][j], 0.f);

    const int KT = K / BK;
    load_tile(0, 0); cp_commit();

    for (int kt = 0; kt < KT; kt++) {
        cp_wait<0>();
        __syncthreads();             // all data of stage kt&1 visible; prev readers done
        if (kt + 1 < KT) load_tile((kt + 1) & 1, kt + 1);
        cp_commit();

        const int s = kt & 1;
#pragma unroll
        for (int kk = 0; kk < 4; kk++) {
            wmma::fragment<wmma::matrix_a, 16, 16, 16, __half, wmma::row_major> af[2];
            wmma::fragment<wmma::matrix_b, 16, 16, 16, __half, wmma::row_major> bf[2];
#pragma unroll
            for (int i = 0; i < 2; i++)
                wmma::load_matrix_sync(af[i], &sm.in.A[s][wr * 32 + i * 16][kk * 16], BK + 8);
#pragma unroll
            for (int j = 0; j < 2; j++)
                wmma::load_matrix_sync(bf[j], &sm.in.B[s][kk * 16][wc * 32 + j * 16], BN + 8);
#pragma unroll
            for (int i = 0; i < 2; i++)
#pragma unroll
                for (int j = 0; j < 2; j++)
                    wmma::mma_sync(acc[i][j], af[i], bf[j], acc[i][j]);
        }
    }
    __syncthreads();                 // before union re-use as Cs

    // spill accumulators to smem
#pragma unroll
    for (int i = 0; i < 2; i++)
#pragma unroll
        for (int j = 0; j < 2; j++)
            wmma::store_matrix_sync(&sm.Cs[wr * 32 + i * 16][wc * 32 + j * 16],
                                    acc[i][j], BN + 4, wmma::mem_row_major);
    __syncthreads();

    if (!FUSED) {
        // bias + relu + fp16 store, 8 cols/thread (STG.128), 4 iterations
#pragma unroll
        for (int e = tid; e < BM * (BN / 8); e += T) {
            const int r = e >> 3, c = (e & 7) << 3;
            __half h8[8];
#pragma unroll
            for (int q = 0; q < 8; q++) {
                float v = fmaxf(sm.Cs[r][c + q] + bias[colBase + c + q], 0.f);
                h8[q] = __float2half(v);
            }
            *reinterpret_cast<int4*>(&C[(size_t)(rowBase + r) * N + colBase + c]) =
                *reinterpret_cast<int4*>(h8);
        }
    } else {
        // thread -> (row, 32-col segment): 64 rows x 2 segs = 128 threads
        const int r = tid >> 1, sc = (tid & 1) << 5;
        float v = 0.f;
#pragma unroll
        for (int i = 0; i < 32; i++) {
            const float h = fmaxf(sm.Cs[r][sc + i] + bs[sc + i], 0.f);
            v = fmaf(h, w3s[sc + i], v);
        }
        sp[r][tid & 1] = v;
        __syncthreads();
        if (tid < BM)
            g_part[(size_t)blockIdx.x * M + rowBase + tid] = sp[tid][0] + sp[tid][1];
    }
}

// ---------------------------------------------------------------------------
// Deterministic final reduce: out[i] = sum of 4 partials + b3. PDL prelude
// hides the launch ramp under gemm2's tail.
// ---------------------------------------------------------------------------
__global__ void __launch_bounds__(256) reduce_kernel(const float* __restrict__ b3,
                                                     float* __restrict__ out)
{
    const int i = blockIdx.x * 256 + threadIdx.x;
    cudaGridDependencySynchronize();             // wait for gemm2 partials
    out[i] = ((g_part[i] + g_part[Bsz + i]) + (g_part[2 * Bsz + i] + g_part[3 * Bsz + i]))
             + b3[0];
}

// ---------------------------------------------------------------------------
extern "C" void kernel_launch(void* const* d_in, const int* in_sizes, int n_in,
                              void* d_out, int out_size)
{
    const int*   x    = (const int*)  d_in[0];
    const float* Wphi = (const float*)d_in[1];
    const float* bphi = (const float*)d_in[2];
    const float* W1   = (const float*)d_in[3];
    const float* b1   = (const float*)d_in[4];
    const float* W2   = (const float*)d_in[5];
    const float* b2   = (const float*)d_in[6];
    const float* W3   = (const float*)d_in[7];
    const float* b3   = (const float*)d_in[8];
    float* out = (float*)d_out;

    __half *hist_p, *h1_p, *Wc_p, *W2_p;
    float *b1eff_p;
    cudaGetSymbolAddress((void**)&hist_p,  g_hist);
    cudaGetSymbolAddress((void**)&h1_p,    g_h1);
    cudaGetSymbolAddress((void**)&Wc_p,    g_Wc);
    cudaGetSymbolAddress((void**)&W2_p,    g_W2);
    cudaGetSymbolAddress((void**)&b1eff_p, g_b1eff);

    // 0: histograms + Wc = Wphi@W1 (HMMA) + W2 convert + b1_eff
    prep_kernel<<<609, 256>>>(x, Wphi, W1, W2, bphi, b1);

    cudaLaunchAttribute at[1];
    at[0].id = cudaLaunchAttributeProgrammaticStreamSerialization;
    at[0].val.programmaticStreamSerializationAllowed = 1;
    cudaLaunchConfig_t cfg = {};
    cfg.attrs = at;
    cfg.numAttrs = 1;
    cfg.stream = 0;

    // 1: h1 = relu(hist @ Wc + b1_eff)   (4096x512)@(512x512) -> 512 blocks
    {
        cfg.gridDim  = dim3(H1d / 64, Bsz / 64);
        cfg.blockDim = dim3(128);
        cudaLaunchKernelEx(&cfg, gemm_tc<false>,
                           (const __half*)hist_p, (const __half*)Wc_p,
                           (const float*)b1eff_p, (const float*)nullptr,
                           (__half*)h1_p, (int)Bsz, (int)H1d, (int)Csz);
    }
    // 2: fused h2 = relu(h1 @ W2 + b2); partials = h2 @ W3 -> 256 blocks
    {
        cfg.gridDim  = dim3(H2d / 64, Bsz / 64);
        cfg.blockDim = dim3(128);
        cudaLaunchKernelEx(&cfg, gemm_tc<true>,
                           (const __half*)h1_p, (const __half*)W2_p,
                           (const float*)b2, (const float*)W3,
                           (__half*)nullptr, (int)Bsz, (int)H2d, (int)H1d);
    }
    // 3: deterministic reduce + b3
    {
        cfg.gridDim  = dim3(Bsz / 256);
        cfg.blockDim = dim3(256);
        cudaLaunchKernelEx(&cfg, reduce_kernel, (const float*)b3, (float*)out);
    }
}

// round 12
// speedup vs baseline: 1.4298x; 1.0782x over previous
#include <cuda_runtime.h>
#include <cuda_fp16.h>
#include <mma.h>

using namespace nvcuda;

#define Bsz  4096
#define Nseq 512
#define Csz  512
#define PHId 128
#define H1d  512
#define H2d  256

// Scratch (__device__ globals; no allocations allowed)
__device__ __half g_hist [Bsz * Csz];    // 4 MB   per-row label histogram (fp16, exact)
__device__ __half g_h1   [Bsz * H1d];    // 4 MB
__device__ float  g_part [4 * Bsz];      // partial dots (deterministic reduce)
__device__ __half g_Wc   [Csz * H1d];    // 512 KB  Wc = Wphi @ W1 (fp16)
__device__ __half g_W2   [H1d * H2d];
__device__ float  g_b1eff[H1d];          // b1 + 512 * (b_phi @ W1), exact fp32
__device__ int    g_cnt  [Bsz / 64];     // per row-block completion counters

// ---------------------------------------------------------------------------
// cp.async helpers (LDGSTS, 16B)
// ---------------------------------------------------------------------------
__device__ __forceinline__ void cp_async16(void* smem, const void* gmem) {
    unsigned s = (unsigned)__cvta_generic_to_shared(smem);
    asm volatile("cp.async.cg.shared.global [%0], [%1], 16;\n" :: "r"(s), "l"(gmem));
}
__device__ __forceinline__ void cp_commit() {
    asm volatile("cp.async.commit_group;\n");
}
template <int NN>
__device__ __forceinline__ void cp_wait() {
    asm volatile("cp.async.wait_group %0;\n" :: "n"(NN));
}
__device__ __forceinline__ void spinwait(volatile int* p, int tgt) {
    while (*p < tgt) __nanosleep(32);
}

// ---------------------------------------------------------------------------
// Prep kernel, block ranges:
//   [0,512)   : per-row histograms (8 rows/block, smem atomics) -> g_hist fp16
//   [512,576) : Wc = Wphi @ W1 via wmma HMMA (fp16 in, fp32 acc), 64x64/block
//   [576,608) : W2 fp32 -> fp16 convert
//   608       : b1_eff = b1 + 512*(b_phi @ W1) fp32; zero g_cnt
// ---------------------------------------------------------------------------
__global__ void __launch_bounds__(256) prep_kernel(const int* __restrict__ x,
                                                   const float* __restrict__ Wphi,
                                                   const float* __restrict__ W1,
                                                   const float* __restrict__ W2,
                                                   const float* __restrict__ bphi,
                                                   const float* __restrict__ b1)
{
    __shared__ __align__(16) char praw[35840];   // 35 KB, aliased per branch
    const int tid = threadIdx.x;

    if (blockIdx.x < 512) {
        int* hs = reinterpret_cast<int*>(praw);  // [8][512]
#pragma unroll
        for (int i = 0; i < 4; i++)
            reinterpret_cast<int4*>(hs)[tid + i * 256] = make_int4(0, 0, 0, 0);
        __syncthreads();

        const int warp = tid >> 5, lane = tid & 31;
        const int row = blockIdx.x * 8 + warp;
        const int4* xr = reinterpret_cast<const int4*>(x + (size_t)row * Nseq);
        int* hw = hs + warp * Csz;
#pragma unroll
        for (int i = 0; i < 4; i++) {            // 128 int4 per row
            const int4 v = xr[lane + i * 32];
            atomicAdd(&hw[v.x], 1);
            atomicAdd(&hw[v.y], 1);
            atomicAdd(&hw[v.z], 1);
            atomicAdd(&hw[v.w], 1);
        }
        __syncthreads();

        // vectorized fp16 conversion: 1024 int4 -> 1024 x 8B stores
        __half* dst = g_hist + (size_t)blockIdx.x * 8 * Csz;
#pragma unroll
        for (int i = 0; i < 4; i++) {
            const int e4 = tid + i * 256;
            const int4 c = reinterpret_cast<const int4*>(hs)[e4];
            __half h4[4] = {__float2half((float)c.x), __float2half((float)c.y),
                            __float2half((float)c.z), __float2half((float)c.w)};
            *reinterpret_cast<uint2*>(&dst[e4 * 4]) = *reinterpret_cast<uint2*>(h4);
        }
    } else if (blockIdx.x < 576) {
        // Wc tile 64x64, K=128, tensor cores. smem: A[64][136]h, B[128][72]h
        const int cb = blockIdx.x - 512;               // 0..63 -> 8x8 tiles
        const int tr = (cb >> 3) * 64, tcc = (cb & 7) * 64;
        __half* sA = reinterpret_cast<__half*>(praw);           // ld 136
        __half* sB = reinterpret_cast<__half*>(praw + 17408);   // ld 72
        float*  sC = reinterpret_cast<float*>(praw);            // ld 68 (aliases sA)

#pragma unroll
        for (int i = 0; i < 8; i++) {
            const int idx = i * 256 + tid;
            const int r = idx >> 5, c4 = (idx & 31) << 2;
            const float4 v = *reinterpret_cast<const float4*>(
                &Wphi[(size_t)(tr + r) * PHId + c4]);
            __half h4[4] = {__float2half(v.x), __float2half(v.y),
                            __float2half(v.z), __float2half(v.w)};
            *reinterpret_cast<uint2*>(&sA[r * 136 + c4]) = *reinterpret_cast<uint2*>(h4);
        }
#pragma unroll
        for (int i = 0; i < 8; i++) {
            const int idx = i * 256 + tid;
            const int r = idx >> 4, c4 = (idx & 15) << 2;
            const float4 v = *reinterpret_cast<const float4*>(
                &W1[(size_t)r * H1d + tcc + c4]);
            __half h4[4] = {__float2half(v.x), __float2half(v.y),
                            __float2half(v.z), __float2half(v.w)};
            *reinterpret_cast<uint2*>(&sB[r * 72 + c4]) = *reinterpret_cast<uint2*>(h4);
        }
        __syncthreads();

        // 8 warps: 2 row-groups x 4 col-groups; warp tile 32x16
        const int wrp = tid >> 5, wr2 = wrp & 1, wc2 = wrp >> 1;
        wmma::fragment<wmma::accumulator, 16, 16, 16, float> ac[2];
        wmma::fill_fragment(ac[0], 0.f);
        wmma::fill_fragment(ac[1], 0.f);
#pragma unroll
        for (int k = 0; k < 8; k++) {
            wmma::fragment<wmma::matrix_a, 16, 16, 16, __half, wmma::row_major> af[2];
            wmma::fragment<wmma::matrix_b, 16, 16, 16, __half, wmma::row_major> bf;
            wmma::load_matrix_sync(af[0], &sA[(wr2 * 32) * 136 + k * 16], 136);
            wmma::load_matrix_sync(af[1], &sA[(wr2 * 32 + 16) * 136 + k * 16], 136);
            wmma::load_matrix_sync(bf, &sB[(k * 16) * 72 + wc2 * 16], 72);
            wmma::mma_sync(ac[0], af[0], bf, ac[0]);
            wmma::mma_sync(ac[1], af[1], bf, ac[1]);
        }
        __syncthreads();       // done reading sA before aliasing as sC
        wmma::store_matrix_sync(&sC[(wr2 * 32) * 68 + wc2 * 16], ac[0], 68,
                                wmma::mem_row_major);
        wmma::store_matrix_sync(&sC[(wr2 * 32 + 16) * 68 + wc2 * 16], ac[1], 68,
                                wmma::mem_row_major);
        __syncthreads();

#pragma unroll
        for (int e = tid; e < 64 * 8; e += 256) {
            const int r = e >> 3, c = (e & 7) << 3;
            __half h8[8];
#pragma unroll
            for (int q = 0; q < 8; q++) h8[q] = __float2half(sC[r * 68 + c + q]);
            *reinterpret_cast<int4*>(&g_Wc[(size_t)(tr + r) * H1d + tcc + c]) =
                *reinterpret_cast<int4*>(h8);
        }
    } else if (blockIdx.x < 608) {
        // W2 convert: 8192 threads, 32768 float4 -> 4 per thread
        const int t = (blockIdx.x - 576) * 256 + tid;
#pragma unroll
        for (int i = 0; i < 4; i++) {
            const int e4 = t + i * 8192;
            const float4 v = reinterpret_cast<const float4*>(W2)[e4];
            __half h4[4] = {__float2half(v.x), __float2half(v.y),
                            __float2half(v.z), __float2half(v.w)};
            *reinterpret_cast<uint2*>(&g_W2[e4 * 4]) = *reinterpret_cast<uint2*>(h4);
        }
    } else {
#pragma unroll
        for (int o = tid; o < H1d; o += 256) {
            float s = 0.f;
            for (int k = 0; k < PHId; k++) s = fmaf(bphi[k], W1[k * H1d + o], s);
            g_b1eff[o] = b1[o] + (float)Nseq * s;
        }
        if (tid < Bsz / 64) g_cnt[tid] = 0;        // zero completion counters
    }
}

// ---------------------------------------------------------------------------
// Pipelined fp16 tensor-core GEMM, fp32 accumulate, fused bias+ReLU epilogue.
// BM=64, BN=64, BK=64; 128 threads = 4 warps (2x2), warp tile 32x32.
// 2-stage cp.async pipeline, ONE __syncthreads per k-iteration.
// FUSED: grid is (4, 68). by<64: producer tile -> partial dots -> g_part,
// release counter. by>=64: 16 reducer blocks (dispatched last), each spins on
// 4 row-block counters, then sums 4 partials per row in fixed order -> out.
// All 272 blocks fit resident simultaneously (6 blocks/SM) -> no deadlock.
// ---------------------------------------------------------------------------
template <bool FUSED>
__global__ void __launch_bounds__(128) gemm_tc(const __half* __restrict__ A,
                                               const __half* __restrict__ B,
                                               const float* __restrict__ bias,
                                               const float* __restrict__ W3,
                                               const float* __restrict__ b3,
                                               __half* __restrict__ C,
                                               float* __restrict__ out,
                                               int M, int N, int K)
{
    constexpr int BM = 64, BN = 64, BK = 64, T = 128;
    __shared__ __align__(16) union USM {
        struct { __half A[2][BM][BK + 8]; __half B[2][BK][BN + 8]; } in;   // 36 KB
        float Cs[BM][BN + 4];
    } sm;
    __shared__ float w3s[BN];
    __shared__ float bs[BN];
    __shared__ float sp[BM][2];

    const int tid = threadIdx.x;

    if (FUSED && blockIdx.y >= 64) {
        // ---- reducer block: 256 rows each, fixed-order deterministic sum ----
        const int rid = (blockIdx.y - 64) * 4 + blockIdx.x;    // 0..15
        volatile int* vc = g_cnt;
        if (tid < 4) spinwait(&vc[rid * 4 + tid], 4);
        __syncthreads();
        __threadfence();
        const float bb = b3[0];
#pragma unroll
        for (int q = 0; q < 2; q++) {
            const int row = rid * 256 + q * 128 + tid;
            const float s = (__ldcg(&g_part[row]) + __ldcg(&g_part[M + row]))
                          + (__ldcg(&g_part[2 * M + row]) + __ldcg(&g_part[3 * M + row]));
            out[row] = s + bb;
        }
        return;
    }

    const int warp = tid >> 5;
    const int wr   = warp & 1;      // row group: 32 rows
    const int wc   = warp >> 1;     // col group: 32 cols
    const int rowBase = blockIdx.y * BM;
    const int colBase = blockIdx.x * BN;

    if (FUSED && tid < BN) {
        w3s[tid] = W3[colBase + tid];
        bs[tid]  = bias[colBase + tid];
    }

    // loader map: 64 rows x 8 chunks(16B) = 512 chunks, 4 per thread
    const int lr = tid >> 3, lc = (tid & 7) << 3;

    auto load_tile = [&](int s, int kt) {
        const __half* Ak = A + (size_t)rowBase * K + kt * BK;
#pragma unroll
        for (int r = 0; r < 4; r++)
            cp_async16(&sm.in.A[s][lr + 16 * r][lc], Ak + (size_t)(lr + 16 * r) * K + lc);
        const __half* Bk = B + (size_t)(kt * BK) * N + colBase;
#pragma unroll
        for (int r = 0; r < 4; r++)
            cp_async16(&sm.in.B[s][lr + 16 * r][lc], Bk + (size_t)(lr + 16 * r) * N + lc);
    };

    wmma::fragment<wmma::accumulator, 16, 16, 16, float> acc[2][2];
#pragma unroll
    for (int i = 0; i < 2; i++)
#pragma unroll
        for (int j = 0; j < 2; j++) wmma::fill_fragment(acc[i][j], 0.f);

    const int KT = K / BK;
    load_tile(0, 0); cp_commit();

    for (int kt = 0; kt < KT; kt++) {
        cp_wait<0>();
        __syncthreads();             // all data of stage kt&1 visible; prev readers done
        if (kt + 1 < KT) load_tile((kt + 1) & 1, kt + 1);
        cp_commit();

        const int s = kt & 1;
#pragma unroll
        for (int kk = 0; kk < 4; kk++) {
            wmma::fragment<wmma::matrix_a, 16, 16, 16, __half, wmma::row_major> af[2];
            wmma::fragment<wmma::matrix_b, 16, 16, 16, __half, wmma::row_major> bf[2];
#pragma unroll
            for (int i = 0; i < 2; i++)
                wmma::load_matrix_sync(af[i], &sm.in.A[s][wr * 32 + i * 16][kk * 16], BK + 8);
#pragma unroll
            for (int j = 0; j < 2; j++)
                wmma::load_matrix_sync(bf[j], &sm.in.B[s][kk * 16][wc * 32 + j * 16], BN + 8);
#pragma unroll
            for (int i = 0; i < 2; i++)
#pragma unroll
                for (int j = 0; j < 2; j++)
                    wmma::mma_sync(acc[i][j], af[i], bf[j], acc[i][j]);
        }
    }
    __syncthreads();                 // before union re-use as Cs

    // spill accumulators to smem
#pragma unroll
    for (int i = 0; i < 2; i++)
#pragma unroll
        for (int j = 0; j < 2; j++)
            wmma::store_matrix_sync(&sm.Cs[wr * 32 + i * 16][wc * 32 + j * 16],
                                    acc[i][j], BN + 4, wmma::mem_row_major);
    __syncthreads();

    if (!FUSED) {
        // bias + relu + fp16 store, 8 cols/thread (STG.128), 4 iterations
#pragma unroll
        for (int e = tid; e < BM * (BN / 8); e += T) {
            const int r = e >> 3, c = (e & 7) << 3;
            __half h8[8];
#pragma unroll
            for (int q = 0; q < 8; q++) {
                float v = fmaxf(sm.Cs[r][c + q] + bias[colBase + c + q], 0.f);
                h8[q] = __float2half(v);
            }
            *reinterpret_cast<int4*>(&C[(size_t)(rowBase + r) * N + colBase + c]) =
                *reinterpret_cast<int4*>(h8);
        }
    } else {
        // thread -> (row, 32-col segment): 64 rows x 2 segs = 128 threads
        const int r = tid >> 1, sc = (tid & 1) << 5;
        float v = 0.f;
#pragma unroll
        for (int i = 0; i < 32; i++) {
            const float h = fmaxf(sm.Cs[r][sc + i] + bs[sc + i], 0.f);
            v = fmaf(h, w3s[sc + i], v);
        }
        sp[r][tid & 1] = v;
        __syncthreads();
        if (tid < BM)
            g_part[(size_t)blockIdx.x * M + rowBase + tid] = sp[tid][0] + sp[tid][1];

        // release: partials visible (fence), then bump row-block counter
        __threadfence();
        __syncthreads();
        if (tid == 0) atomicAdd(&g_cnt[blockIdx.y], 1);
    }
}

// ---------------------------------------------------------------------------
extern "C" void kernel_launch(void* const* d_in, const int* in_sizes, int n_in,
                              void* d_out, int out_size)
{
    const int*   x    = (const int*)  d_in[0];
    const float* Wphi = (const float*)d_in[1];
    const float* bphi = (const float*)d_in[2];
    const float* W1   = (const float*)d_in[3];
    const float* b1   = (const float*)d_in[4];
    const float* W2   = (const float*)d_in[5];
    const float* b2   = (const float*)d_in[6];
    const float* W3   = (const float*)d_in[7];
    const float* b3   = (const float*)d_in[8];
    float* out = (float*)d_out;

    __half *hist_p, *h1_p, *Wc_p, *W2_p;
    float *b1eff_p;
    cudaGetSymbolAddress((void**)&hist_p,  g_hist);
    cudaGetSymbolAddress((void**)&h1_p,    g_h1);
    cudaGetSymbolAddress((void**)&Wc_p,    g_Wc);
    cudaGetSymbolAddress((void**)&W2_p,    g_W2);
    cudaGetSymbolAddress((void**)&b1eff_p, g_b1eff);

    // 0: histograms + Wc = Wphi@W1 (HMMA) + W2 convert + b1_eff + counters
    prep_kernel<<<609, 256>>>(x, Wphi, W1, W2, bphi, b1);

    // 1: h1 = relu(hist @ Wc + b1_eff)   (4096x512)@(512x512) -> 512 blocks
    {
        dim3 grid(H1d / 64, Bsz / 64);
        gemm_tc<false><<<grid, 128>>>(hist_p, Wc_p, b1eff_p, nullptr, nullptr,
                                      h1_p, nullptr, Bsz, H1d, Csz);
    }
    // 2: fused h2 = relu(h1 @ W2 + b2); partials -> in-grid reducers -> out
    {
        dim3 grid(H2d / 64, Bsz / 64 + 4);   // 256 producers + 16 reducers
        gemm_tc<true><<<grid, 128>>>(h1_p, W2_p, b2, W3, b3,
                                     nullptr, out, Bsz, H2d, H1d);
    }
}